// round 1
// baseline (speedup 1.0000x reference)
#include <cuda_runtime.h>
#include <cuda_bf16.h>
#include <cstdint>

// Problem constants
#define BATCH 64
#define SEQ   257
#define HEADS 16
#define HDIM  64
#define CDIM  1024
#define MROWS (BATCH * SEQ)      // 16448
#define QKV_N (3 * CDIM)         // 3072

// ---------------- scratch (device globals; no cudaMalloc allowed) ----------
__device__ float g_Q [(size_t)BATCH * HEADS * SEQ * HDIM];
__device__ float g_K [(size_t)BATCH * HEADS * SEQ * HDIM];
__device__ float g_V [(size_t)BATCH * HEADS * SEQ * HDIM];
__device__ float g_AO[(size_t)MROWS * CDIM];

// ---------------- helpers ---------------------------------------------------
__device__ __forceinline__ uint32_t f2tf32(float f) {
    uint32_t u;
    asm("cvt.rna.tf32.f32 %0, %1;" : "=r"(u) : "f"(f));
    return u;
}

__device__ __forceinline__ void mma_tf32(float c[4], const uint32_t a[4], const uint32_t b[2]) {
    asm volatile(
        "mma.sync.aligned.m16n8k8.row.col.f32.tf32.tf32.f32 "
        "{%0,%1,%2,%3}, {%4,%5,%6,%7}, {%8,%9}, {%0,%1,%2,%3};"
        : "+f"(c[0]), "+f"(c[1]), "+f"(c[2]), "+f"(c[3])
        : "r"(a[0]), "r"(a[1]), "r"(a[2]), "r"(a[3]), "r"(b[0]), "r"(b[1]));
}

// ---------------- tf32 GEMM: C = A[M,K] * W[N,K]^T (+epilogue) --------------
// MODE 0: QKV  (A = x, W = qkv_weight; scatter into g_Q/g_K/g_V with bias, q*0.125)
// MODE 1: proj (A = g_AO, W = proj_weight; out = C + proj_bias)
template<int MODE>
__global__ __launch_bounds__(256)
void gemm_tf32(const float* __restrict__ A, const float* __restrict__ W,
               const float* __restrict__ bias_a, const float* __restrict__ bias_b,
               float* __restrict__ out, int M, int N, int K)
{
    __shared__ float As[128][36];
    __shared__ float Bs[128][36];

    const int tid  = threadIdx.x;
    const int warp = tid >> 5, lane = tid & 31;
    const int wm = warp & 3, wn = warp >> 2;       // 4 x 2 warp grid
    const int g = lane >> 2, c = lane & 3;
    const int bm = blockIdx.y, bn = blockIdx.x;

    float acc[2][8][4];
    #pragma unroll
    for (int mt = 0; mt < 2; mt++)
        #pragma unroll
        for (int nt = 0; nt < 8; nt++)
            #pragma unroll
            for (int r = 0; r < 4; r++) acc[mt][nt][r] = 0.f;

    const float* Abase = (MODE == 0) ? A : g_AO;
    const float* Ag = Abase + (size_t)bm * 128 * K;
    const float* Wg = W + (size_t)bn * 128 * K;

    for (int kt = 0; kt < K; kt += 32) {
        #pragma unroll
        for (int i = 0; i < 4; i++) {
            int f   = i * 256 + tid;
            int row = f >> 3, kq = f & 7;
            int grow = bm * 128 + row;
            float4 av = make_float4(0.f, 0.f, 0.f, 0.f);
            if (grow < M) av = *(const float4*)(Ag + (size_t)row * K + kt + kq * 4);
            float4 ac;
            ac.x = __uint_as_float(f2tf32(av.x));
            ac.y = __uint_as_float(f2tf32(av.y));
            ac.z = __uint_as_float(f2tf32(av.z));
            ac.w = __uint_as_float(f2tf32(av.w));
            *(float4*)&As[row][kq * 4] = ac;

            float4 bv = *(const float4*)(Wg + (size_t)row * K + kt + kq * 4);
            float4 bc;
            bc.x = __uint_as_float(f2tf32(bv.x));
            bc.y = __uint_as_float(f2tf32(bv.y));
            bc.z = __uint_as_float(f2tf32(bv.z));
            bc.w = __uint_as_float(f2tf32(bv.w));
            *(float4*)&Bs[row][kq * 4] = bc;
        }
        __syncthreads();

        #pragma unroll
        for (int ks = 0; ks < 32; ks += 8) {
            uint32_t afr[2][4], bfr[8][2];
            #pragma unroll
            for (int mt = 0; mt < 2; mt++) {
                const float* ap = &As[wm * 32 + mt * 16 + g][ks + c];
                afr[mt][0] = __float_as_uint(ap[0]);
                afr[mt][1] = __float_as_uint(ap[8 * 36]);
                afr[mt][2] = __float_as_uint(ap[4]);
                afr[mt][3] = __float_as_uint(ap[8 * 36 + 4]);
            }
            #pragma unroll
            for (int nt = 0; nt < 8; nt++) {
                const float* bp = &Bs[wn * 64 + nt * 8 + g][ks + c];
                bfr[nt][0] = __float_as_uint(bp[0]);
                bfr[nt][1] = __float_as_uint(bp[4]);
            }
            #pragma unroll
            for (int mt = 0; mt < 2; mt++)
                #pragma unroll
                for (int nt = 0; nt < 8; nt++)
                    mma_tf32(acc[mt][nt], afr[mt], bfr[nt]);
        }
        __syncthreads();
    }

    // epilogue
    #pragma unroll
    for (int mt = 0; mt < 2; mt++)
        #pragma unroll
        for (int nt = 0; nt < 8; nt++)
            #pragma unroll
            for (int r = 0; r < 4; r++) {
                int row = bm * 128 + wm * 32 + mt * 16 + g + ((r >= 2) ? 8 : 0);
                int col = bn * 128 + wn * 64 + nt * 8 + 2 * c + (r & 1);
                if (row >= M) continue;
                float val = acc[mt][nt][r];
                if (MODE == 0) {
                    int b = row / SEQ, t = row - b * SEQ;
                    int sec = col >> 10, cc = col & 1023;
                    int h = cc >> 6, d = cc & 63;
                    size_t o = (((size_t)b * HEADS + h) * SEQ + t) * HDIM + d;
                    if (sec == 0)      g_Q[o] = (val + bias_a[cc]) * 0.125f;
                    else if (sec == 1) g_K[o] = val;
                    else               g_V[o] = val + bias_b[cc];
                } else {
                    out[(size_t)row * N + col] = val + bias_a[col];
                }
            }
}

// ---------------- attention: per (b,h), K/V resident in smem ---------------
#define KV_STRIDE 68
#define SMEM_FLOATS (2 * SEQ * KV_STRIDE + 8 * 264)

__global__ __launch_bounds__(256)
void attn_kernel(const float* __restrict__ table, const int* __restrict__ relidx)
{
    extern __shared__ float sm[];
    float* Ks   = sm;
    float* Vs   = sm + SEQ * KV_STRIDE;
    float* pbuf = Vs + SEQ * KV_STRIDE;

    const int bh = blockIdx.x;
    const int b = bh >> 4, h = bh & 15;
    const int tid = threadIdx.x;
    const int warp = tid >> 5, lane = tid & 31;

    // load K,V tiles (257 x 64) into padded smem
    const float4* kg = (const float4*)(g_K + (size_t)bh * SEQ * HDIM);
    const float4* vg = (const float4*)(g_V + (size_t)bh * SEQ * HDIM);
    for (int f = tid; f < SEQ * 16; f += 256) {
        int j = f >> 4, dq = f & 15;
        *(float4*)&Ks[j * KV_STRIDE + dq * 4] = kg[f];
        *(float4*)&Vs[j * KV_STRIDE + dq * 4] = vg[f];
    }
    __syncthreads();

    const float* qbase = g_Q + (size_t)bh * SEQ * HDIM;
    float* pw = pbuf + warp * 264;

    for (int r = warp; r < SEQ; r += 8) {
        // q row broadcast into registers
        float4 q4[16];
        const float4* qp = (const float4*)(qbase + (size_t)r * HDIM);
        #pragma unroll
        for (int i = 0; i < 16; i++) q4[i] = qp[i];

        const int* irow = relidx + r * SEQ;
        float sreg[9];
        float mx = -3.0e38f;
        #pragma unroll
        for (int i = 0; i < 9; i++) {
            int j = lane + 32 * i;
            if (j < SEQ) {
                const float* kr = Ks + j * KV_STRIDE;
                float s = 0.f;
                #pragma unroll
                for (int d = 0; d < 16; d++) {
                    float4 kv = *(const float4*)(kr + 4 * d);
                    s = fmaf(q4[d].x, kv.x, s);
                    s = fmaf(q4[d].y, kv.y, s);
                    s = fmaf(q4[d].z, kv.z, s);
                    s = fmaf(q4[d].w, kv.w, s);
                }
                s += __ldg(table + irow[j] * HEADS + h);
                sreg[i] = s;
                mx = fmaxf(mx, s);
            } else sreg[i] = -3.0e38f;
        }
        #pragma unroll
        for (int o = 16; o; o >>= 1) mx = fmaxf(mx, __shfl_xor_sync(0xffffffffu, mx, o));

        float sum = 0.f;
        #pragma unroll
        for (int i = 0; i < 9; i++) {
            int j = lane + 32 * i;
            if (j < SEQ) {
                float p = __expf(sreg[i] - mx);
                pw[j] = p;
                sum += p;
            }
        }
        #pragma unroll
        for (int o = 16; o; o >>= 1) sum += __shfl_xor_sync(0xffffffffu, sum, o);
        float inv = 1.0f / sum;
        __syncwarp();

        // PV: lane owns dims {2*lane, 2*lane+1}
        float o0 = 0.f, o1 = 0.f;
        #pragma unroll 4
        for (int j = 0; j < SEQ; j++) {
            float p = pw[j];
            float2 vv = *(const float2*)(Vs + j * KV_STRIDE + 2 * lane);
            o0 = fmaf(p, vv.x, o0);
            o1 = fmaf(p, vv.y, o1);
        }
        float2 res = make_float2(o0 * inv, o1 * inv);
        *(float2*)(g_AO + ((size_t)b * SEQ + r) * CDIM + h * HDIM + 2 * lane) = res;
        __syncwarp();
    }
}

// ---------------- launch ----------------------------------------------------
extern "C" void kernel_launch(void* const* d_in, const int* in_sizes, int n_in,
                              void* d_out, int out_size)
{
    const float* x    = (const float*)d_in[0];   // [64,257,1024]
    const float* qkvw = (const float*)d_in[1];   // [3072,1024]
    const float* qb   = (const float*)d_in[2];   // [1024]
    const float* vb   = (const float*)d_in[3];   // [1024]
    const float* tbl  = (const float*)d_in[4];   // [964,16]
    const float* pwgt = (const float*)d_in[5];   // [1024,1024]
    const float* pb   = (const float*)d_in[6];   // [1024]
    const int*   ridx = (const int*)d_in[7];     // [257,257]
    float* out = (float*)d_out;                  // [64,257,1024]

    static_assert(SMEM_FLOATS * 4 == 148256, "smem size");
    cudaFuncSetAttribute(attn_kernel, cudaFuncAttributeMaxDynamicSharedMemorySize,
                         SMEM_FLOATS * 4);

    dim3 gq(QKV_N / 128, (MROWS + 127) / 128);   // 24 x 129
    gemm_tf32<0><<<gq, 256>>>(x, qkvw, qb, vb, nullptr, MROWS, QKV_N, CDIM);

    attn_kernel<<<BATCH * HEADS, 256, SMEM_FLOATS * 4>>>(tbl, ridx);

    dim3 gp(CDIM / 128, (MROWS + 127) / 128);    // 8 x 129
    gemm_tf32<1><<<gp, 256>>>(nullptr, pwgt, pb, nullptr, out, MROWS, CDIM, CDIM);
}

// round 2
// speedup vs baseline: 1.7883x; 1.7883x over previous
#include <cuda_runtime.h>
#include <cuda_bf16.h>
#include <cstdint>

// Problem constants
#define BATCH 64
#define SEQ   257
#define HEADS 16
#define HDIM  64
#define CDIM  1024
#define MROWS (BATCH * SEQ)      // 16448
#define QKV_N (3 * CDIM)         // 3072

// ---------------- scratch (device globals; no cudaMalloc allowed) ----------
__device__ float g_Q [(size_t)BATCH * HEADS * SEQ * HDIM];
__device__ float g_K [(size_t)BATCH * HEADS * SEQ * HDIM];
__device__ float g_V [(size_t)BATCH * HEADS * SEQ * HDIM];
__device__ float g_AO[(size_t)MROWS * CDIM];

// ---------------- helpers ---------------------------------------------------
__device__ __forceinline__ uint32_t f2tf32(float f) {
    uint32_t u;
    asm("cvt.rna.tf32.f32 %0, %1;" : "=r"(u) : "f"(f));
    return u;
}

__device__ __forceinline__ void mma_tf32(float c[4], const uint32_t a[4], const uint32_t b[2]) {
    asm volatile(
        "mma.sync.aligned.m16n8k8.row.col.f32.tf32.tf32.f32 "
        "{%0,%1,%2,%3}, {%4,%5,%6,%7}, {%8,%9}, {%0,%1,%2,%3};"
        : "+f"(c[0]), "+f"(c[1]), "+f"(c[2]), "+f"(c[3])
        : "r"(a[0]), "r"(a[1]), "r"(a[2]), "r"(a[3]), "r"(b[0]), "r"(b[1]));
}

__device__ __forceinline__ void cp16(float* s, const float* g, bool pred) {
    uint32_t sa = (uint32_t)__cvta_generic_to_shared(s);
    int sz = pred ? 16 : 0;
    asm volatile("cp.async.cg.shared.global [%0], [%1], 16, %2;\n"
                 :: "r"(sa), "l"(g), "r"(sz));
}

#define STAGES 3
#define TILE_F 4608   // 128 rows * 36 floats
#define GEMM_SMEM (2 * STAGES * TILE_F * 4)  // 110592 bytes

// ---------------- tf32 GEMM: C = A[M,K] * W[N,K]^T (+epilogue) --------------
// MODE 0: QKV  (A = x, W = qkv_weight; scatter into g_Q/g_K/g_V with bias, q*0.125)
// MODE 1: proj (A = g_AO, W = proj_weight; out = C + proj_bias)
template<int MODE>
__global__ __launch_bounds__(256)
void gemm_tf32(const float* __restrict__ A, const float* __restrict__ W,
               const float* __restrict__ bias_a, const float* __restrict__ bias_b,
               float* __restrict__ out, int M, int N, int K)
{
    extern __shared__ float sh[];
    float* Asm = sh;
    float* Bsm = sh + STAGES * TILE_F;

    const int tid  = threadIdx.x;
    const int warp = tid >> 5, lane = tid & 31;
    const int wm = warp & 3, wn = warp >> 2;       // 4 x 2 warp grid
    const int g = lane >> 2, c = lane & 3;
    const int bm = blockIdx.y, bn = blockIdx.x;

    float acc[2][8][4];
    #pragma unroll
    for (int mt = 0; mt < 2; mt++)
        #pragma unroll
        for (int nt = 0; nt < 8; nt++)
            #pragma unroll
            for (int r = 0; r < 4; r++) acc[mt][nt][r] = 0.f;

    const float* Abase = (MODE == 0) ? A : g_AO;
    const float* Ag = Abase + (size_t)bm * 128 * K;
    const float* Wg = W + (size_t)bn * 128 * K;

    const int nk = K / 32;

    auto issue_tile = [&](int t) {
        if (t < nk) {
            const int kt = t * 32;
            float* as = Asm + (t % STAGES) * TILE_F;
            float* bs = Bsm + (t % STAGES) * TILE_F;
            #pragma unroll
            for (int i = 0; i < 4; i++) {
                int f = i * 256 + tid;
                int row = f >> 3, kq = f & 7;
                bool pv = (bm * 128 + row) < M;
                cp16(as + row * 36 + kq * 4, Ag + (size_t)row * K + kt + kq * 4, pv);
                cp16(bs + row * 36 + kq * 4, Wg + (size_t)row * K + kt + kq * 4, true);
            }
        }
        asm volatile("cp.async.commit_group;" ::: "memory");
    };

    issue_tile(0);
    issue_tile(1);

    for (int t = 0; t < nk; t++) {
        asm volatile("cp.async.wait_group 1;" ::: "memory");
        __syncthreads();
        issue_tile(t + 2);

        const float* as = Asm + (t % STAGES) * TILE_F;
        const float* bs = Bsm + (t % STAGES) * TILE_F;
        #pragma unroll
        for (int ks = 0; ks < 32; ks += 8) {
            uint32_t afr[2][4], bfr[8][2];
            #pragma unroll
            for (int mt = 0; mt < 2; mt++) {
                const float* ap = as + (wm * 32 + mt * 16 + g) * 36 + ks + c;
                afr[mt][0] = f2tf32(ap[0]);
                afr[mt][1] = f2tf32(ap[8 * 36]);
                afr[mt][2] = f2tf32(ap[4]);
                afr[mt][3] = f2tf32(ap[8 * 36 + 4]);
            }
            #pragma unroll
            for (int nt = 0; nt < 8; nt++) {
                const float* bp = bs + (wn * 64 + nt * 8 + g) * 36 + ks + c;
                bfr[nt][0] = f2tf32(bp[0]);
                bfr[nt][1] = f2tf32(bp[4]);
            }
            #pragma unroll
            for (int mt = 0; mt < 2; mt++)
                #pragma unroll
                for (int nt = 0; nt < 8; nt++)
                    mma_tf32(acc[mt][nt], afr[mt], bfr[nt]);
        }
    }

    // epilogue
    #pragma unroll
    for (int mt = 0; mt < 2; mt++)
        #pragma unroll
        for (int nt = 0; nt < 8; nt++)
            #pragma unroll
            for (int r = 0; r < 4; r++) {
                int row = bm * 128 + wm * 32 + mt * 16 + g + ((r >= 2) ? 8 : 0);
                int col = bn * 128 + wn * 64 + nt * 8 + 2 * c + (r & 1);
                if (row >= M) continue;
                float val = acc[mt][nt][r];
                if (MODE == 0) {
                    int b = row / SEQ, t = row - b * SEQ;
                    int sec = col >> 10, cc = col & 1023;
                    int h = cc >> 6, d = cc & 63;
                    size_t o = (((size_t)b * HEADS + h) * SEQ + t) * HDIM + d;
                    if (sec == 0)      g_Q[o] = (val + bias_a[cc]) * 0.125f;
                    else if (sec == 1) g_K[o] = val;
                    else               g_V[o] = val + bias_b[cc];
                } else {
                    out[(size_t)row * N + col] = val + bias_a[col];
                }
            }
}

// ---------------- attention: per (b,h), K/V resident in smem ---------------
// 4 q-rows per warp per pass: amortizes K/V smem reads 4x.
#define KV_STRIDE 68
#define PB 264
#define ATTN_SMEM_F (2 * SEQ * KV_STRIDE + 8 * 4 * PB + 964)  // 44364 floats
#define ATTN_SMEM   (ATTN_SMEM_F * 4)                          // 177456 bytes

__global__ __launch_bounds__(256)
void attn_kernel(const float* __restrict__ table, const int* __restrict__ relidx)
{
    extern __shared__ float sm[];
    float* Ks   = sm;
    float* Vs   = sm + SEQ * KV_STRIDE;
    float* pbuf = Vs + SEQ * KV_STRIDE;
    float* tbl  = pbuf + 8 * 4 * PB;

    const int bh = blockIdx.x;
    const int b = bh >> 4, h = bh & 15;
    const int tid = threadIdx.x;
    const int warp = tid >> 5, lane = tid & 31;

    // load K,V tiles (257 x 64) into padded smem
    const float4* kg = (const float4*)(g_K + (size_t)bh * SEQ * HDIM);
    const float4* vg = (const float4*)(g_V + (size_t)bh * SEQ * HDIM);
    for (int f = tid; f < SEQ * 16; f += 256) {
        int j = f >> 4, dq = f & 15;
        *(float4*)&Ks[j * KV_STRIDE + dq * 4] = kg[f];
        *(float4*)&Vs[j * KV_STRIDE + dq * 4] = vg[f];
    }
    // stage this head's bias-table column
    for (int rel = tid; rel < 964; rel += 256)
        tbl[rel] = __ldg(table + rel * HEADS + h);
    __syncthreads();

    const float4* qp = (const float4*)(g_Q + (size_t)bh * SEQ * HDIM);
    float* pw = pbuf + warp * (4 * PB);

    for (int it = 0; it < 9; ++it) {
        const int rbase = it * 32 + warp * 4;
        if (rbase >= SEQ) break;
        const int nv = min(4, SEQ - rbase);

        // ---- QK^T: 4 rows x 257 cols, K read once per 4 rows ----
        float s[4][9];
        #pragma unroll
        for (int rr = 0; rr < 4; rr++)
            #pragma unroll
            for (int i = 0; i < 9; i++) s[rr][i] = 0.f;

        #pragma unroll
        for (int dc = 0; dc < 16; dc++) {
            float4 qv[4];
            #pragma unroll
            for (int rr = 0; rr < 4; rr++)
                qv[rr] = (rr < nv) ? qp[(rbase + rr) * 16 + dc]
                                   : make_float4(0.f, 0.f, 0.f, 0.f);
            #pragma unroll
            for (int i = 0; i < 9; i++) {
                int j = lane + 32 * i;
                if (j < SEQ) {
                    float4 kv = *(const float4*)(Ks + j * KV_STRIDE + 4 * dc);
                    #pragma unroll
                    for (int rr = 0; rr < 4; rr++) {
                        s[rr][i] = fmaf(qv[rr].x, kv.x, s[rr][i]);
                        s[rr][i] = fmaf(qv[rr].y, kv.y, s[rr][i]);
                        s[rr][i] = fmaf(qv[rr].z, kv.z, s[rr][i]);
                        s[rr][i] = fmaf(qv[rr].w, kv.w, s[rr][i]);
                    }
                }
            }
        }

        // ---- bias + softmax per row ----
        float inv[4];
        #pragma unroll
        for (int rr = 0; rr < 4; rr++) {
            if (rr >= nv) break;
            const int r = rbase + rr;
            const int* irow = relidx + r * SEQ;
            float mx = -3.0e38f;
            #pragma unroll
            for (int i = 0; i < 9; i++) {
                int j = lane + 32 * i;
                if (j < SEQ) {
                    s[rr][i] += tbl[irow[j]];
                    mx = fmaxf(mx, s[rr][i]);
                }
            }
            #pragma unroll
            for (int o = 16; o; o >>= 1) mx = fmaxf(mx, __shfl_xor_sync(0xffffffffu, mx, o));
            float sum = 0.f;
            #pragma unroll
            for (int i = 0; i < 9; i++) {
                int j = lane + 32 * i;
                if (j < SEQ) {
                    float p = __expf(s[rr][i] - mx);
                    pw[rr * PB + j] = p;
                    sum += p;
                }
            }
            #pragma unroll
            for (int o = 16; o; o >>= 1) sum += __shfl_xor_sync(0xffffffffu, sum, o);
            inv[rr] = 1.0f / sum;
        }
        __syncwarp();

        // ---- PV: 4 rows share each V float2 load; lane owns dims {2l,2l+1} ----
        float o0[4] = {0.f, 0.f, 0.f, 0.f};
        float o1[4] = {0.f, 0.f, 0.f, 0.f};
        #pragma unroll 2
        for (int j4 = 0; j4 < 64; j4++) {
            const int j0 = 4 * j4;
            float4 pv4[4];
            #pragma unroll
            for (int rr = 0; rr < 4; rr++)
                pv4[rr] = *(const float4*)(pw + rr * PB + j0);
            #pragma unroll
            for (int u = 0; u < 4; u++) {
                float2 vv = *(const float2*)(Vs + (j0 + u) * KV_STRIDE + 2 * lane);
                #pragma unroll
                for (int rr = 0; rr < 4; rr++) {
                    float p = (&pv4[rr].x)[u];
                    o0[rr] = fmaf(p, vv.x, o0[rr]);
                    o1[rr] = fmaf(p, vv.y, o1[rr]);
                }
            }
        }
        {   // tail j = 256
            float2 vv = *(const float2*)(Vs + 256 * KV_STRIDE + 2 * lane);
            #pragma unroll
            for (int rr = 0; rr < 4; rr++) {
                float p = pw[rr * PB + 256];
                o0[rr] = fmaf(p, vv.x, o0[rr]);
                o1[rr] = fmaf(p, vv.y, o1[rr]);
            }
        }

        #pragma unroll
        for (int rr = 0; rr < 4; rr++) {
            if (rr >= nv) break;
            const int r = rbase + rr;
            float2 res = make_float2(o0[rr] * inv[rr], o1[rr] * inv[rr]);
            *(float2*)(g_AO + ((size_t)b * SEQ + r) * CDIM + h * HDIM + 2 * lane) = res;
        }
        __syncwarp();
    }
}

// ---------------- launch ----------------------------------------------------
extern "C" void kernel_launch(void* const* d_in, const int* in_sizes, int n_in,
                              void* d_out, int out_size)
{
    const float* x    = (const float*)d_in[0];   // [64,257,1024]
    const float* qkvw = (const float*)d_in[1];   // [3072,1024]
    const float* qb   = (const float*)d_in[2];   // [1024]
    const float* vb   = (const float*)d_in[3];   // [1024]
    const float* tbl  = (const float*)d_in[4];   // [964,16]
    const float* pwgt = (const float*)d_in[5];   // [1024,1024]
    const float* pb   = (const float*)d_in[6];   // [1024]
    const int*   ridx = (const int*)d_in[7];     // [257,257]
    float* out = (float*)d_out;                  // [64,257,1024]

    cudaFuncSetAttribute(gemm_tf32<0>, cudaFuncAttributeMaxDynamicSharedMemorySize, GEMM_SMEM);
    cudaFuncSetAttribute(gemm_tf32<1>, cudaFuncAttributeMaxDynamicSharedMemorySize, GEMM_SMEM);
    cudaFuncSetAttribute(attn_kernel,  cudaFuncAttributeMaxDynamicSharedMemorySize, ATTN_SMEM);

    dim3 gq(QKV_N / 128, (MROWS + 127) / 128);   // 24 x 129
    gemm_tf32<0><<<gq, 256, GEMM_SMEM>>>(x, qkvw, qb, vb, nullptr, MROWS, QKV_N, CDIM);

    attn_kernel<<<BATCH * HEADS, 256, ATTN_SMEM>>>(tbl, ridx);

    dim3 gp(CDIM / 128, (MROWS + 127) / 128);    // 8 x 129
    gemm_tf32<1><<<gp, 256, GEMM_SMEM>>>(nullptr, pwgt, pb, nullptr, out, MROWS, CDIM, CDIM);
}

// round 3
// speedup vs baseline: 2.1679x; 1.2123x over previous
#include <cuda_runtime.h>
#include <cuda_bf16.h>
#include <cstdint>

// Problem constants
#define BATCH 64
#define SEQ   257
#define HEADS 16
#define HDIM  64
#define CDIM  1024
#define MROWS (BATCH * SEQ)      // 16448
#define QKV_N (3 * CDIM)         // 3072

typedef unsigned long long ull;

// ---------------- scratch (device globals; no cudaMalloc allowed) ----------
__device__ float g_Q [(size_t)BATCH * HEADS * SEQ * HDIM];
__device__ float g_K [(size_t)BATCH * HEADS * SEQ * HDIM];
__device__ float g_V [(size_t)BATCH * HEADS * SEQ * HDIM];
__device__ float g_AO[(size_t)MROWS * CDIM];
__device__ float g_Xc[(size_t)MROWS * CDIM];          // tf32-rounded x
__device__ float g_Wq[(size_t)QKV_N * CDIM];          // tf32-rounded qkv_weight
__device__ float g_Wp[(size_t)CDIM * CDIM];           // tf32-rounded proj_weight

// ---------------- helpers ---------------------------------------------------
__device__ __forceinline__ uint32_t f2tf32(float f) {
    uint32_t u;
    asm("cvt.rna.tf32.f32 %0, %1;" : "=r"(u) : "f"(f));
    return u;
}

__device__ __forceinline__ void mma_tf32(float c[4], const uint32_t a[4], const uint32_t b[2]) {
    asm volatile(
        "mma.sync.aligned.m16n8k8.row.col.f32.tf32.tf32.f32 "
        "{%0,%1,%2,%3}, {%4,%5,%6,%7}, {%8,%9}, {%0,%1,%2,%3};"
        : "+f"(c[0]), "+f"(c[1]), "+f"(c[2]), "+f"(c[3])
        : "r"(a[0]), "r"(a[1]), "r"(a[2]), "r"(a[3]), "r"(b[0]), "r"(b[1]));
}

__device__ __forceinline__ void cp16(float* s, const float* g, bool pred) {
    uint32_t sa = (uint32_t)__cvta_generic_to_shared(s);
    int sz = pred ? 16 : 0;
    asm volatile("cp.async.cg.shared.global [%0], [%1], 16, %2;\n"
                 :: "r"(sa), "l"(g), "r"(sz));
}

// packed f32x2 ops (Blackwell FFMA2 path)
__device__ __forceinline__ void fma2(ull& c, ull a, ull b) {
    asm("fma.rn.f32x2 %0, %1, %2, %3;" : "=l"(c) : "l"(a), "l"(b), "l"(c));
}
__device__ __forceinline__ void add2(ull& c, ull a) {
    asm("add.rn.f32x2 %0, %1, %2;" : "=l"(c) : "l"(a), "l"(c));
}
__device__ __forceinline__ ull pk2(float x, float y) {
    ull r; asm("mov.b64 %0, {%1,%2};" : "=l"(r) : "f"(x), "f"(y)); return r;
}
__device__ __forceinline__ float2 upk(ull v) {
    float2 f; asm("mov.b64 {%0,%1}, %2;" : "=f"(f.x), "=f"(f.y) : "l"(v)); return f;
}

// ---------------- tf32 pre-round copy ---------------------------------------
__global__ void cvt4_kernel(const float4* __restrict__ in, float4* __restrict__ out, int n4)
{
    int i = blockIdx.x * blockDim.x + threadIdx.x;
    if (i < n4) {
        float4 v = in[i];
        v.x = __uint_as_float(f2tf32(v.x));
        v.y = __uint_as_float(f2tf32(v.y));
        v.z = __uint_as_float(f2tf32(v.z));
        v.w = __uint_as_float(f2tf32(v.w));
        out[i] = v;
    }
}

#define STAGES 3
#define TILE_F 4608   // 128 rows * 36 floats
#define GEMM_SMEM (2 * STAGES * TILE_F * 4)  // 110592 bytes

// ---------------- tf32 GEMM: C = A[M,K] * W[N,K]^T (+epilogue) --------------
// Inputs already tf32-rounded. MODE 0: QKV (scatter Q/K/V). MODE 1: proj.
template<int MODE>
__global__ __launch_bounds__(256, 2)
void gemm_tf32(const float* __restrict__ bias_a, const float* __restrict__ bias_b,
               float* __restrict__ out, int M, int N, int K)
{
    extern __shared__ float sh[];
    float* Asm = sh;
    float* Bsm = sh + STAGES * TILE_F;

    const int tid  = threadIdx.x;
    const int warp = tid >> 5, lane = tid & 31;
    const int wm = warp & 3, wn = warp >> 2;       // 4 x 2 warp grid
    const int g = lane >> 2, c = lane & 3;
    const int bm = blockIdx.y, bn = blockIdx.x;

    float acc[2][8][4];
    #pragma unroll
    for (int mt = 0; mt < 2; mt++)
        #pragma unroll
        for (int nt = 0; nt < 8; nt++)
            #pragma unroll
            for (int r = 0; r < 4; r++) acc[mt][nt][r] = 0.f;

    const float* Ag = ((MODE == 0) ? g_Xc : g_AO) + (size_t)bm * 128 * K;
    const float* Wg = ((MODE == 0) ? g_Wq : g_Wp) + (size_t)bn * 128 * K;

    const int nk = K / 32;

    auto issue_tile = [&](int t) {
        if (t < nk) {
            const int kt = t * 32;
            float* as = Asm + (t % STAGES) * TILE_F;
            float* bs = Bsm + (t % STAGES) * TILE_F;
            #pragma unroll
            for (int i = 0; i < 4; i++) {
                int f = i * 256 + tid;
                int row = f >> 3, kq = f & 7;
                bool pv = (bm * 128 + row) < M;
                cp16(as + row * 36 + kq * 4, Ag + (size_t)row * K + kt + kq * 4, pv);
                cp16(bs + row * 36 + kq * 4, Wg + (size_t)row * K + kt + kq * 4, true);
            }
        }
        asm volatile("cp.async.commit_group;" ::: "memory");
    };

    issue_tile(0);
    issue_tile(1);

    for (int t = 0; t < nk; t++) {
        asm volatile("cp.async.wait_group 1;" ::: "memory");
        __syncthreads();
        issue_tile(t + 2);

        const float* as = Asm + (t % STAGES) * TILE_F;
        const float* bs = Bsm + (t % STAGES) * TILE_F;
        #pragma unroll
        for (int ks = 0; ks < 32; ks += 8) {
            uint32_t afr[2][4], bfr[8][2];
            #pragma unroll
            for (int mt = 0; mt < 2; mt++) {
                const float* ap = as + (wm * 32 + mt * 16 + g) * 36 + ks + c;
                afr[mt][0] = __float_as_uint(ap[0]);
                afr[mt][1] = __float_as_uint(ap[8 * 36]);
                afr[mt][2] = __float_as_uint(ap[4]);
                afr[mt][3] = __float_as_uint(ap[8 * 36 + 4]);
            }
            #pragma unroll
            for (int nt = 0; nt < 8; nt++) {
                const float* bp = bs + (wn * 64 + nt * 8 + g) * 36 + ks + c;
                bfr[nt][0] = __float_as_uint(bp[0]);
                bfr[nt][1] = __float_as_uint(bp[4]);
            }
            #pragma unroll
            for (int mt = 0; mt < 2; mt++)
                #pragma unroll
                for (int nt = 0; nt < 8; nt++)
                    mma_tf32(acc[mt][nt], afr[mt], bfr[nt]);
        }
    }

    // epilogue
    #pragma unroll
    for (int mt = 0; mt < 2; mt++)
        #pragma unroll
        for (int nt = 0; nt < 8; nt++)
            #pragma unroll
            for (int r = 0; r < 4; r++) {
                int row = bm * 128 + wm * 32 + mt * 16 + g + ((r >= 2) ? 8 : 0);
                int col = bn * 128 + wn * 64 + nt * 8 + 2 * c + (r & 1);
                if (row >= M) continue;
                float val = acc[mt][nt][r];
                if (MODE == 0) {
                    int b = row / SEQ, t = row - b * SEQ;
                    int sec = col >> 10, cc = col & 1023;
                    int h = cc >> 6, d = cc & 63;
                    size_t o = (((size_t)b * HEADS + h) * SEQ + t) * HDIM + d;
                    if (sec == 0)      g_Q[o] = (val + bias_a[cc]) * 0.125f;
                    else if (sec == 1) g_K[o] = val;
                    else               g_V[o] = val + bias_b[cc];
                } else {
                    out[(size_t)row * N + col] = val + bias_a[col];
                }
            }
}

// ---------------- attention: per (b,h), K/V resident in smem ---------------
// 4 q-rows per warp per pass; packed f32x2 FMA throughout.
#define KV_STRIDE 68
#define PB 264
#define ATTN_SMEM_F (2 * SEQ * KV_STRIDE + 8 * 4 * PB + 964)  // 44364 floats
#define ATTN_SMEM   (ATTN_SMEM_F * 4)                          // 177456 bytes

__global__ __launch_bounds__(256)
void attn_kernel(const float* __restrict__ table, const int* __restrict__ relidx)
{
    extern __shared__ float sm[];
    float* Ks   = sm;
    float* Vs   = sm + SEQ * KV_STRIDE;
    float* pbuf = Vs + SEQ * KV_STRIDE;
    float* tbl  = pbuf + 8 * 4 * PB;

    const int bh = blockIdx.x;
    const int b = bh >> 4, h = bh & 15;
    const int tid = threadIdx.x;
    const int warp = tid >> 5, lane = tid & 31;

    // load K,V tiles (257 x 64) into padded smem
    const float4* kg = (const float4*)(g_K + (size_t)bh * SEQ * HDIM);
    const float4* vg = (const float4*)(g_V + (size_t)bh * SEQ * HDIM);
    for (int f = tid; f < SEQ * 16; f += 256) {
        int j = f >> 4, dq = f & 15;
        *(float4*)&Ks[j * KV_STRIDE + dq * 4] = kg[f];
        *(float4*)&Vs[j * KV_STRIDE + dq * 4] = vg[f];
    }
    // stage this head's bias-table column
    for (int rel = tid; rel < 964; rel += 256)
        tbl[rel] = __ldg(table + rel * HEADS + h);
    __syncthreads();

    const ulonglong2* qpu = (const ulonglong2*)(g_Q + (size_t)bh * SEQ * HDIM);
    float* pw = pbuf + warp * (4 * PB);

    for (int it = 0; it < 9; ++it) {
        const int rbase = it * 32 + warp * 4;
        if (rbase >= SEQ) break;
        const int nv = min(4, SEQ - rbase);

        // ---- QK^T with f32x2: s2[rr][i] accumulates (even,odd) comps ----
        ull s2[4][9];
        #pragma unroll
        for (int rr = 0; rr < 4; rr++)
            #pragma unroll
            for (int i = 0; i < 9; i++) s2[rr][i] = 0ull;

        #pragma unroll
        for (int dc = 0; dc < 16; dc++) {
            ulonglong2 q2[4];
            #pragma unroll
            for (int rr = 0; rr < 4; rr++)
                q2[rr] = (rr < nv) ? qpu[(rbase + rr) * 16 + dc]
                                   : make_ulonglong2(0ull, 0ull);
            #pragma unroll
            for (int i = 0; i < 9; i++) {
                int j = lane + 32 * i;
                if (j < SEQ) {
                    ulonglong2 kv = *(const ulonglong2*)(Ks + j * KV_STRIDE + 4 * dc);
                    #pragma unroll
                    for (int rr = 0; rr < 4; rr++) {
                        fma2(s2[rr][i], q2[rr].x, kv.x);
                        fma2(s2[rr][i], q2[rr].y, kv.y);
                    }
                }
            }
        }
        // horizontal add of packed pairs
        float s[4][9];
        #pragma unroll
        for (int rr = 0; rr < 4; rr++)
            #pragma unroll
            for (int i = 0; i < 9; i++) {
                float2 t = upk(s2[rr][i]);
                s[rr][i] = t.x + t.y;
            }

        // ---- bias + softmax per row ----
        float inv[4];
        #pragma unroll
        for (int rr = 0; rr < 4; rr++) {
            if (rr >= nv) break;
            const int r = rbase + rr;
            const int* irow = relidx + r * SEQ;
            float mx = -3.0e38f;
            #pragma unroll
            for (int i = 0; i < 9; i++) {
                int j = lane + 32 * i;
                if (j < SEQ) {
                    s[rr][i] += tbl[irow[j]];
                    mx = fmaxf(mx, s[rr][i]);
                }
            }
            #pragma unroll
            for (int o = 16; o; o >>= 1) mx = fmaxf(mx, __shfl_xor_sync(0xffffffffu, mx, o));
            float sum = 0.f;
            #pragma unroll
            for (int i = 0; i < 9; i++) {
                int j = lane + 32 * i;
                if (j < SEQ) {
                    float p = __expf(s[rr][i] - mx);
                    pw[rr * PB + j] = p;
                    sum += p;
                }
            }
            #pragma unroll
            for (int o = 16; o; o >>= 1) sum += __shfl_xor_sync(0xffffffffu, sum, o);
            inv[rr] = 1.0f / sum;
        }
        __syncwarp();

        // ---- PV with f32x2: lane owns 4 dims, half-warps split the j range ----
        const int half = lane >> 4;            // 0: j in [0,128), 1: j in [128,256)+tail
        const int d0 = (lane & 15) * 4;
        ull a01[4] = {0,0,0,0}, a23[4] = {0,0,0,0};
        const int jbeg = half * 128;

        #pragma unroll 2
        for (int jb = 0; jb < 32; jb++) {
            const int j0 = jbeg + jb * 4;
            float4 pv4[4];
            #pragma unroll
            for (int rr = 0; rr < 4; rr++)
                pv4[rr] = *(const float4*)(pw + rr * PB + j0);
            #pragma unroll
            for (int u = 0; u < 4; u++) {
                ulonglong2 vv = *(const ulonglong2*)(Vs + (j0 + u) * KV_STRIDE + d0);
                #pragma unroll
                for (int rr = 0; rr < 4; rr++) {
                    float p = (&pv4[rr].x)[u];
                    ull p2 = pk2(p, p);
                    fma2(a01[rr], p2, vv.x);
                    fma2(a23[rr], p2, vv.y);
                }
            }
        }
        if (half) {   // tail j = 256
            ulonglong2 vv = *(const ulonglong2*)(Vs + 256 * KV_STRIDE + d0);
            #pragma unroll
            for (int rr = 0; rr < 4; rr++) {
                float p = pw[rr * PB + 256];
                ull p2 = pk2(p, p);
                fma2(a01[rr], p2, vv.x);
                fma2(a23[rr], p2, vv.y);
            }
        }
        // combine the two half-warp partial sums
        #pragma unroll
        for (int rr = 0; rr < 4; rr++) {
            add2(a01[rr], __shfl_xor_sync(0xffffffffu, a01[rr], 16));
            add2(a23[rr], __shfl_xor_sync(0xffffffffu, a23[rr], 16));
        }
        if (half == 0) {
            #pragma unroll
            for (int rr = 0; rr < 4; rr++) {
                if (rr >= nv) break;
                const int r = rbase + rr;
                float2 lo = upk(a01[rr]);
                float2 hi = upk(a23[rr]);
                float4 res;   // write tf32-rounded so proj GEMM needs no cvt
                res.x = __uint_as_float(f2tf32(lo.x * inv[rr]));
                res.y = __uint_as_float(f2tf32(lo.y * inv[rr]));
                res.z = __uint_as_float(f2tf32(hi.x * inv[rr]));
                res.w = __uint_as_float(f2tf32(hi.y * inv[rr]));
                *(float4*)(g_AO + ((size_t)b * SEQ + r) * CDIM + h * HDIM + d0) = res;
            }
        }
        __syncwarp();
    }
}

// ---------------- launch ----------------------------------------------------
extern "C" void kernel_launch(void* const* d_in, const int* in_sizes, int n_in,
                              void* d_out, int out_size)
{
    const float* x    = (const float*)d_in[0];   // [64,257,1024]
    const float* qkvw = (const float*)d_in[1];   // [3072,1024]
    const float* qb   = (const float*)d_in[2];   // [1024]
    const float* vb   = (const float*)d_in[3];   // [1024]
    const float* tbl  = (const float*)d_in[4];   // [964,16]
    const float* pwgt = (const float*)d_in[5];   // [1024,1024]
    const float* pb   = (const float*)d_in[6];   // [1024]
    const int*   ridx = (const int*)d_in[7];     // [257,257]
    float* out = (float*)d_out;                  // [64,257,1024]

    cudaFuncSetAttribute(gemm_tf32<0>, cudaFuncAttributeMaxDynamicSharedMemorySize, GEMM_SMEM);
    cudaFuncSetAttribute(gemm_tf32<1>, cudaFuncAttributeMaxDynamicSharedMemorySize, GEMM_SMEM);
    cudaFuncSetAttribute(attn_kernel,  cudaFuncAttributeMaxDynamicSharedMemorySize, ATTN_SMEM);

    float *xc, *wq, *wp;
    cudaGetSymbolAddress((void**)&xc, g_Xc);
    cudaGetSymbolAddress((void**)&wq, g_Wq);
    cudaGetSymbolAddress((void**)&wp, g_Wp);

    // pre-round inputs to tf32 (removes all cvt from GEMM mainloops)
    {
        int n4;
        n4 = MROWS * CDIM / 4;
        cvt4_kernel<<<(n4 + 255) / 256, 256>>>((const float4*)x, (float4*)xc, n4);
        n4 = QKV_N * CDIM / 4;
        cvt4_kernel<<<(n4 + 255) / 256, 256>>>((const float4*)qkvw, (float4*)wq, n4);
        n4 = CDIM * CDIM / 4;
        cvt4_kernel<<<(n4 + 255) / 256, 256>>>((const float4*)pwgt, (float4*)wp, n4);
    }

    dim3 gq(QKV_N / 128, (MROWS + 127) / 128);   // 24 x 129
    gemm_tf32<0><<<gq, 256, GEMM_SMEM>>>(qb, vb, nullptr, MROWS, QKV_N, CDIM);

    attn_kernel<<<BATCH * HEADS, 256, ATTN_SMEM>>>(tbl, ridx);

    dim3 gp(CDIM / 128, (MROWS + 127) / 128);    // 8 x 129
    gemm_tf32<1><<<gp, 256, GEMM_SMEM>>>(pb, nullptr, out, MROWS, CDIM, CDIM);
}

// round 5
// speedup vs baseline: 2.4524x; 1.1312x over previous
#include <cuda_runtime.h>
#include <cuda_bf16.h>
#include <cstdint>

// Problem constants
#define BATCH 64
#define SEQ   257
#define HEADS 16
#define HDIM  64
#define CDIM  1024
#define MROWS (BATCH * SEQ)      // 16448
#define QKV_N (3 * CDIM)         // 3072

typedef unsigned long long ull;

// ---------------- scratch (device globals; no cudaMalloc allowed) ----------
__device__ float g_Q [(size_t)BATCH * HEADS * SEQ * HDIM];   // [bh][j][d] tf32-rounded, scaled
__device__ float g_K [(size_t)BATCH * HEADS * SEQ * HDIM];   // [bh][j][d] tf32-rounded
__device__ float g_V [(size_t)BATCH * HEADS * SEQ * HDIM];   // [bh][d][j]  TRANSPOSED, tf32-rounded
__device__ float g_AO[(size_t)MROWS * CDIM];                 // tf32-rounded
__device__ float g_Xc[(size_t)MROWS * CDIM];          // tf32-rounded x
__device__ float g_Wq[(size_t)QKV_N * CDIM];          // tf32-rounded qkv_weight
__device__ float g_Wp[(size_t)CDIM * CDIM];           // tf32-rounded proj_weight

// ---------------- helpers ---------------------------------------------------
__device__ __forceinline__ uint32_t f2tf32(float f) {
    uint32_t u;
    asm("cvt.rna.tf32.f32 %0, %1;" : "=r"(u) : "f"(f));
    return u;
}
__device__ __forceinline__ float r2t(float f) { return __uint_as_float(f2tf32(f)); }

__device__ __forceinline__ void mma_tf32(float c[4], const uint32_t a[4], const uint32_t b[2]) {
    asm volatile(
        "mma.sync.aligned.m16n8k8.row.col.f32.tf32.tf32.f32 "
        "{%0,%1,%2,%3}, {%4,%5,%6,%7}, {%8,%9}, {%0,%1,%2,%3};"
        : "+f"(c[0]), "+f"(c[1]), "+f"(c[2]), "+f"(c[3])
        : "r"(a[0]), "r"(a[1]), "r"(a[2]), "r"(a[3]), "r"(b[0]), "r"(b[1]));
}

__device__ __forceinline__ void cp16(float* s, const float* g, bool pred) {
    uint32_t sa = (uint32_t)__cvta_generic_to_shared(s);
    int sz = pred ? 16 : 0;
    asm volatile("cp.async.cg.shared.global [%0], [%1], 16, %2;\n"
                 :: "r"(sa), "l"(g), "r"(sz));
}

// ---------------- tf32 pre-round copy ---------------------------------------
__global__ void cvt4_kernel(const float4* __restrict__ in, float4* __restrict__ out, int n4)
{
    int i = blockIdx.x * blockDim.x + threadIdx.x;
    if (i < n4) {
        float4 v = in[i];
        v.x = r2t(v.x); v.y = r2t(v.y); v.z = r2t(v.z); v.w = r2t(v.w);
        out[i] = v;
    }
}

#define STAGES 3
#define TILE_F 4608   // 128 rows * 36 floats
#define GEMM_SMEM (2 * STAGES * TILE_F * 4)  // 110592 bytes

// ---------------- tf32 GEMM: C = A[M,K] * W[N,K]^T (+epilogue) --------------
// Inputs already tf32-rounded. MODE 0: QKV (scatter Q/K/Vt). MODE 1: proj.
template<int MODE>
__global__ __launch_bounds__(256, 2)
void gemm_tf32(const float* __restrict__ bias_a, const float* __restrict__ bias_b,
               float* __restrict__ out, int M, int N, int K)
{
    extern __shared__ float sh[];
    float* Asm = sh;
    float* Bsm = sh + STAGES * TILE_F;

    const int tid  = threadIdx.x;
    const int warp = tid >> 5, lane = tid & 31;
    const int wm = warp & 3, wn = warp >> 2;       // 4 x 2 warp grid
    const int g = lane >> 2, c = lane & 3;
    const int bm = blockIdx.y, bn = blockIdx.x;

    float acc[2][8][4];
    #pragma unroll
    for (int mt = 0; mt < 2; mt++)
        #pragma unroll
        for (int nt = 0; nt < 8; nt++)
            #pragma unroll
            for (int r = 0; r < 4; r++) acc[mt][nt][r] = 0.f;

    const float* Ag = ((MODE == 0) ? g_Xc : g_AO) + (size_t)bm * 128 * K;
    const float* Wg = ((MODE == 0) ? g_Wq : g_Wp) + (size_t)bn * 128 * K;

    const int nk = K / 32;

    auto issue_tile = [&](int t) {
        if (t < nk) {
            const int kt = t * 32;
            float* as = Asm + (t % STAGES) * TILE_F;
            float* bs = Bsm + (t % STAGES) * TILE_F;
            #pragma unroll
            for (int i = 0; i < 4; i++) {
                int f = i * 256 + tid;
                int row = f >> 3, kq = f & 7;
                bool pv = (bm * 128 + row) < M;
                cp16(as + row * 36 + kq * 4, Ag + (size_t)row * K + kt + kq * 4, pv);
                cp16(bs + row * 36 + kq * 4, Wg + (size_t)row * K + kt + kq * 4, true);
            }
        }
        asm volatile("cp.async.commit_group;" ::: "memory");
    };

    issue_tile(0);
    issue_tile(1);

    for (int t = 0; t < nk; t++) {
        asm volatile("cp.async.wait_group 1;" ::: "memory");
        __syncthreads();
        issue_tile(t + 2);

        const float* as = Asm + (t % STAGES) * TILE_F;
        const float* bs = Bsm + (t % STAGES) * TILE_F;
        #pragma unroll
        for (int ks = 0; ks < 32; ks += 8) {
            uint32_t afr[2][4], bfr[8][2];
            #pragma unroll
            for (int mt = 0; mt < 2; mt++) {
                const float* ap = as + (wm * 32 + mt * 16 + g) * 36 + ks + c;
                afr[mt][0] = __float_as_uint(ap[0]);
                afr[mt][1] = __float_as_uint(ap[8 * 36]);
                afr[mt][2] = __float_as_uint(ap[4]);
                afr[mt][3] = __float_as_uint(ap[8 * 36 + 4]);
            }
            #pragma unroll
            for (int nt = 0; nt < 8; nt++) {
                const float* bp = bs + (wn * 64 + nt * 8 + g) * 36 + ks + c;
                bfr[nt][0] = __float_as_uint(bp[0]);
                bfr[nt][1] = __float_as_uint(bp[4]);
            }
            #pragma unroll
            for (int mt = 0; mt < 2; mt++)
                #pragma unroll
                for (int nt = 0; nt < 8; nt++)
                    mma_tf32(acc[mt][nt], afr[mt], bfr[nt]);
        }
    }

    // epilogue
    #pragma unroll
    for (int mt = 0; mt < 2; mt++)
        #pragma unroll
        for (int nt = 0; nt < 8; nt++)
            #pragma unroll
            for (int r = 0; r < 4; r++) {
                int row = bm * 128 + wm * 32 + mt * 16 + g + ((r >= 2) ? 8 : 0);
                int col = bn * 128 + wn * 64 + nt * 8 + 2 * c + (r & 1);
                if (row >= M) continue;
                float val = acc[mt][nt][r];
                if (MODE == 0) {
                    int b = row / SEQ, tt = row - b * SEQ;
                    int sec = col >> 10, cc = col & 1023;
                    int h = cc >> 6, d = cc & 63;
                    int bh = b * HEADS + h;
                    if (sec == 0)
                        g_Q[(((size_t)bh) * SEQ + tt) * HDIM + d] = r2t((val + bias_a[cc]) * 0.125f);
                    else if (sec == 1)
                        g_K[(((size_t)bh) * SEQ + tt) * HDIM + d] = r2t(val);
                    else  // V transposed: [bh][d][j]
                        g_V[((size_t)bh * HDIM + d) * SEQ + tt] = r2t(val + bias_b[cc]);
                } else {
                    out[(size_t)row * N + col] = val + bias_a[col];
                }
            }
}

// ---------------- attention: tensor-core (mma.sync tf32) --------------------
// One CTA per (b,h). K [264x68] and Vt [64x268] in smem.
// Each warp owns one 16-row m-tile (17 tiles over 8 warps).
#define AK_STR 68
#define AV_STR 268
#define AP_STR 132
#define ATTN_SMEM_F (264 * AK_STR + 64 * AV_STR + 8 * 16 * AP_STR + 964)  // 52964
#define ATTN_SMEM   (ATTN_SMEM_F * 4)                                      // 211856

__global__ __launch_bounds__(256)
void attn_tc(const float* __restrict__ table, const int* __restrict__ relidx)
{
    extern __shared__ float sm[];
    float* Ks  = sm;                      // [264][68]
    float* Vts = sm + 264 * AK_STR;       // [64][268]
    float* Ps  = Vts + 64 * AV_STR;       // [8][16][132]
    float* tbl = Ps + 8 * 16 * AP_STR;    // [964]

    const int bh = blockIdx.x;
    const int b = bh >> 4, h = bh & 15;
    const int tid = threadIdx.x;
    const int warp = tid >> 5, lane = tid & 31;
    const int g = lane >> 2, c = lane & 3;

    // --- stage K, Vt, bias column ---
    const float* kg  = g_K + (size_t)bh * SEQ * HDIM;   // [257][64]
    const float* vtg = g_V + (size_t)bh * SEQ * HDIM;   // [64][257]
    for (int f = tid; f < SEQ * 16; f += 256) {
        int j = f >> 4, dq = f & 15;
        *(float4*)&Ks[j * AK_STR + dq * 4] = *(const float4*)(kg + f * 4);
    }
    for (int f = tid; f < 64 * 257; f += 256) {
        int d = f / 257, j = f - d * 257;
        Vts[d * AV_STR + j] = vtg[f];
    }
    for (int f = tid; f < 64 * 8; f += 256) {           // zero V pad cols 257..264
        int d = f >> 3;
        Vts[d * AV_STR + 257 + (f & 7)] = 0.f;
    }
    for (int rel = tid; rel < 964; rel += 256)
        tbl[rel] = __ldg(table + rel * HEADS + h);
    __syncthreads();

    const float* qg = g_Q + (size_t)bh * SEQ * HDIM;
    float* Pw = Ps + warp * (16 * AP_STR);

    for (int mt = warp; mt < 17; mt += 8) {
        const int rowbase = mt * 16;
        const int r0 = rowbase + g, r1 = rowbase + 8 + g;

        // Q fragments (rows r0, r1), guarded
        uint32_t qf[8][4];
        #pragma unroll
        for (int ks = 0; ks < 8; ks++) {
            qf[ks][0] = (r0 < SEQ) ? __float_as_uint(qg[r0 * 64 + ks * 8 + c])     : 0u;
            qf[ks][1] = (r1 < SEQ) ? __float_as_uint(qg[r1 * 64 + ks * 8 + c])     : 0u;
            qf[ks][2] = (r0 < SEQ) ? __float_as_uint(qg[r0 * 64 + ks * 8 + c + 4]) : 0u;
            qf[ks][3] = (r1 < SEQ) ? __float_as_uint(qg[r1 * 64 + ks * 8 + c + 4]) : 0u;
        }

        // ---- S = Q K^T : 33 n-tiles x 8 k-steps ----
        float sacc[33][4];
        #pragma unroll
        for (int nt = 0; nt < 33; nt++) {
            sacc[nt][0] = sacc[nt][1] = sacc[nt][2] = sacc[nt][3] = 0.f;
        }
        #pragma unroll
        for (int nt = 0; nt < 33; nt++) {
            #pragma unroll
            for (int ks = 0; ks < 8; ks++) {
                uint32_t bf[2];
                const float* bp = Ks + (nt * 8 + g) * AK_STR + ks * 8 + c;
                bf[0] = __float_as_uint(bp[0]);
                bf[1] = __float_as_uint(bp[4]);
                mma_tf32(sacc[nt], qf[ks], bf);
            }
        }

        // ---- bias + softmax (rows r0 via regs {0,1}, r1 via {2,3}) ----
        float inv[2];
        #pragma unroll
        for (int hf = 0; hf < 2; hf++) {
            const int qrow = hf ? r1 : r0;
            const int* irow = relidx + (qrow < SEQ ? qrow : 0) * SEQ;
            float mx = -3.0e38f;
            #pragma unroll
            for (int nt = 0; nt < 33; nt++)
                #pragma unroll
                for (int u = 0; u < 2; u++) {
                    int col = nt * 8 + 2 * c + u;
                    float s = (col < SEQ) ? sacc[nt][2 * hf + u] + tbl[irow[col]]
                                          : -3.0e38f;
                    sacc[nt][2 * hf + u] = s;
                    mx = fmaxf(mx, s);
                }
            mx = fmaxf(mx, __shfl_xor_sync(0xffffffffu, mx, 1));
            mx = fmaxf(mx, __shfl_xor_sync(0xffffffffu, mx, 2));
            float sum = 0.f;
            #pragma unroll
            for (int nt = 0; nt < 33; nt++)
                #pragma unroll
                for (int u = 0; u < 2; u++) {
                    int col = nt * 8 + 2 * c + u;
                    float p = (col < SEQ) ? __expf(sacc[nt][2 * hf + u] - mx) : 0.f;
                    sacc[nt][2 * hf + u] = p;
                    sum += p;
                }
            sum += __shfl_xor_sync(0xffffffffu, sum, 1);
            sum += __shfl_xor_sync(0xffffffffu, sum, 2);
            inv[hf] = 1.0f / sum;
        }

        // ---- O = P V : 3 k-chunks through per-warp P smem tile ----
        float oacc[8][4];
        #pragma unroll
        for (int nt = 0; nt < 8; nt++) {
            oacc[nt][0] = oacc[nt][1] = oacc[nt][2] = oacc[nt][3] = 0.f;
        }
        #pragma unroll
        for (int ch = 0; ch < 3; ch++) {
            const int j0 = ch * 128;
            const int nks = (ch == 2) ? 1 : 16;
            const int ntb = j0 / 8;
            #pragma unroll
            for (int nt2 = 0; nt2 < 16; nt2++) {
                if (nt2 >= nks) break;      // folds at compile time (ch unrolled)
                const int nt = ntb + nt2;
                #pragma unroll
                for (int u = 0; u < 2; u++) {
                    int col = nt * 8 + 2 * c + u - j0;
                    Pw[g * AP_STR + col]       = r2t(sacc[nt][u]);
                    Pw[(g + 8) * AP_STR + col] = r2t(sacc[nt][2 + u]);
                }
            }
            __syncwarp();
            #pragma unroll
            for (int ks = 0; ks < 16; ks++) {
                if (ks >= nks) break;
                uint32_t af[4];
                const float* ap  = Pw + g * AP_STR + ks * 8 + c;
                const float* ap2 = Pw + (g + 8) * AP_STR + ks * 8 + c;
                af[0] = __float_as_uint(ap[0]);
                af[1] = __float_as_uint(ap2[0]);
                af[2] = __float_as_uint(ap[4]);
                af[3] = __float_as_uint(ap2[4]);
                #pragma unroll
                for (int nt = 0; nt < 8; nt++) {
                    uint32_t bf[2];
                    const float* bp = Vts + (nt * 8 + g) * AV_STR + j0 + ks * 8 + c;
                    bf[0] = __float_as_uint(bp[0]);
                    bf[1] = __float_as_uint(bp[4]);
                    mma_tf32(oacc[nt], af, bf);
                }
            }
            __syncwarp();
        }

        // ---- store O (tf32-rounded for proj GEMM) ----
        #pragma unroll
        for (int nt = 0; nt < 8; nt++)
            #pragma unroll
            for (int r = 0; r < 4; r++) {
                const int row = (r >= 2) ? r1 : r0;
                if (row < SEQ) {
                    const int d = nt * 8 + 2 * c + (r & 1);
                    float v = oacc[nt][r] * inv[r >> 1];
                    g_AO[((size_t)b * SEQ + row) * CDIM + h * 64 + d] = r2t(v);
                }
            }
    }
}

// ---------------- launch ----------------------------------------------------
extern "C" void kernel_launch(void* const* d_in, const int* in_sizes, int n_in,
                              void* d_out, int out_size)
{
    const float* x    = (const float*)d_in[0];   // [64,257,1024]
    const float* qkvw = (const float*)d_in[1];   // [3072,1024]
    const float* qb   = (const float*)d_in[2];   // [1024]
    const float* vb   = (const float*)d_in[3];   // [1024]
    const float* tbl  = (const float*)d_in[4];   // [964,16]
    const float* pwgt = (const float*)d_in[5];   // [1024,1024]
    const float* pb   = (const float*)d_in[6];   // [1024]
    const int*   ridx = (const int*)d_in[7];     // [257,257]
    float* out = (float*)d_out;                  // [64,257,1024]

    cudaFuncSetAttribute(gemm_tf32<0>, cudaFuncAttributeMaxDynamicSharedMemorySize, GEMM_SMEM);
    cudaFuncSetAttribute(gemm_tf32<1>, cudaFuncAttributeMaxDynamicSharedMemorySize, GEMM_SMEM);
    cudaFuncSetAttribute(attn_tc,      cudaFuncAttributeMaxDynamicSharedMemorySize, ATTN_SMEM);

    float *xc, *wq, *wp;
    cudaGetSymbolAddress((void**)&xc, g_Xc);
    cudaGetSymbolAddress((void**)&wq, g_Wq);
    cudaGetSymbolAddress((void**)&wp, g_Wp);

    // pre-round inputs to tf32 (removes all cvt from GEMM mainloops)
    {
        int n4;
        n4 = MROWS * CDIM / 4;
        cvt4_kernel<<<(n4 + 255) / 256, 256>>>((const float4*)x, (float4*)xc, n4);
        n4 = QKV_N * CDIM / 4;
        cvt4_kernel<<<(n4 + 255) / 256, 256>>>((const float4*)qkvw, (float4*)wq, n4);
        n4 = CDIM * CDIM / 4;
        cvt4_kernel<<<(n4 + 255) / 256, 256>>>((const float4*)pwgt, (float4*)wp, n4);
    }

    dim3 gq(QKV_N / 128, (MROWS + 127) / 128);   // 24 x 129
    gemm_tf32<0><<<gq, 256, GEMM_SMEM>>>(qb, vb, nullptr, MROWS, QKV_N, CDIM);

    attn_tc<<<BATCH * HEADS, 256, ATTN_SMEM>>>(tbl, ridx);

    dim3 gp(CDIM / 128, (MROWS + 127) / 128);    // 8 x 129
    gemm_tf32<1><<<gp, 256, GEMM_SMEM>>>(pb, nullptr, out, MROWS, CDIM, CDIM);
}